// round 7
// baseline (speedup 1.0000x reference)
#include <cuda_runtime.h>
#include <math.h>

#define NB   128
#define NHID 512
#define GATE_ELEMS (NB * NHID)   // 65536
#define NSPLIT 32
#define GEMM2_BLOCKS 16          // 8 j-tiles * 2 m-tiles (paired p/o, full-K)
#define GATE_BLOCKS 256
#define TRACE_BLOCKS 32768

// ---------------- device scratch (no allocations allowed) ----------------
__device__ float d_part[NSPLIT][NB * 1024];       // split-K partials, 16 MB
__device__ float d_hv2[GEMM2_BLOCKS][64 * 512];   // per-GEMM2-CTA h tiles, 2 MB
__device__ int   d_open;
__device__ int   d_tick;

// ---------------------------------------------------------------------------
// Gate math from pre-activations (shared by all recompute sites).
// ---------------------------------------------------------------------------
struct Gate { float g, r, h, a, cg, cr; };

__device__ __forceinline__ Gate gate_math(float gpre, float rpre, float hl)
{
    Gate o;
    float g = tanhf(gpre);
    g = fmaxf(g, 0.f);                       // relu(tanh)
    const float r  = tanhf(rpre);
    const float Hg = (g > 0.f) ? 1.f : 0.f;  // clip(ceil(g),0,1), g in [0,1]
    const float dg = (1.f - g * g) * Hg;
    const float dr = 1.f - r * r;
    o.g = g; o.r = r;
    o.h  = g * r + (1.f - g) * hl;
    o.a  = 1.f - g;
    o.cg = dg * (r - hl);
    o.cr = dr * g;
    return o;
}

// serial 32-partial sums for one (b,j): gpre/rpre (bias added by caller)
__device__ __forceinline__ void sum_partials(int og, float& gp, float& rp)
{
    #pragma unroll
    for (int s = 0; s < NSPLIT; s++) {
        gp += d_part[s][og];
        rp += d_part[s][og + 512];
    }
}

// ---------------------------------------------------------------------------
// Launch 1: split-K dual GEMM for g/r pre-activations.
//   CTA tile 128m x 128n, BK=16, 256 threads, 8x8 register tile, double
//   buffered. grid = (8 n-tiles, 32 splits) = 256 CTAs -> 2 resident per SM.
//   split s: half = s>>4 (x | h_last), kb = (s&15)*32, k-chunk = 32.
// ---------------------------------------------------------------------------
__global__ void __launch_bounds__(256, 2) k_gemm1(
    const float* __restrict__ x, const float* __restrict__ h_last,
    const float* __restrict__ w_gx, const float* __restrict__ w_gh,
    const float* __restrict__ w_rx, const float* __restrict__ w_rh)
{
    __shared__ float As[2][16 * 132];   // [stage][k][m(128)+pad]
    __shared__ float Ws[2][16 * 132];   // [stage][k][n(128)+pad]

    const int tid = threadIdx.x;
    if (blockIdx.x == 0 && blockIdx.y == 0 && tid == 0) {
        d_open = 0;                      // reset counters for launch 2
        d_tick = 0;
    }

    const int n0   = blockIdx.x * 128;   // n in [0,1024)
    const int s    = blockIdx.y;         // split 0..31
    const int half = s >> 4;             // 0: x-part, 1: h-part
    const int kb   = (s & 15) * 32;      // offset within the 512-wide half

    const bool g2 = (n0 >= 512);
    const int  j0 = g2 ? (n0 - 512) : n0;
    const float* A = half ? h_last : x;
    const float* W = g2 ? (half ? w_rh : w_rx) : (half ? w_gh : w_gx);
    float* outp    = d_part[s];

    const int lr = tid & 127;            // row (m for A, n for W)
    const int ka = (tid >> 7) << 3;      // k offset: 0 or 8 (two float4 each)

    const int tx = tid & 15;             // n-dir (8 cols)
    const int ty = tid >> 4;             // m-dir (8 rows)

    const float* Aload = A + lr * 512 + kb + ka;
    const float* Wload = W + (j0 + lr) * 512 + kb + ka;

    float acc[8][8];
    #pragma unroll
    for (int i = 0; i < 8; i++)
        #pragma unroll
        for (int j = 0; j < 8; j++) acc[i][j] = 0.f;

    float4 a0 = *(const float4*)(Aload);
    float4 a1 = *(const float4*)(Aload + 4);
    float4 w0 = *(const float4*)(Wload);
    float4 w1 = *(const float4*)(Wload + 4);

    {
        float* as = As[0]; float* ws = Ws[0];
        as[(ka+0)*132+lr]=a0.x; as[(ka+1)*132+lr]=a0.y; as[(ka+2)*132+lr]=a0.z; as[(ka+3)*132+lr]=a0.w;
        as[(ka+4)*132+lr]=a1.x; as[(ka+5)*132+lr]=a1.y; as[(ka+6)*132+lr]=a1.z; as[(ka+7)*132+lr]=a1.w;
        ws[(ka+0)*132+lr]=w0.x; ws[(ka+1)*132+lr]=w0.y; ws[(ka+2)*132+lr]=w0.z; ws[(ka+3)*132+lr]=w0.w;
        ws[(ka+4)*132+lr]=w1.x; ws[(ka+5)*132+lr]=w1.y; ws[(ka+6)*132+lr]=w1.z; ws[(ka+7)*132+lr]=w1.w;
    }
    __syncthreads();

    #pragma unroll 1
    for (int t = 0; t < 2; t++) {        // 2 k-tiles of 16 (k-chunk = 32)
        const int cur = t & 1;
        const float* as = As[cur];
        const float* ws = Ws[cur];

        if (t < 1) {                      // prefetch next k-tile
            a0 = *(const float4*)(Aload + 16);
            a1 = *(const float4*)(Aload + 20);
            w0 = *(const float4*)(Wload + 16);
            w1 = *(const float4*)(Wload + 20);
        }

        #pragma unroll
        for (int kk = 0; kk < 16; kk++) {
            float a[8], w[8];
            *(float4*)&a[0] = *(const float4*)(as + kk * 132 + (ty << 3));
            *(float4*)&a[4] = *(const float4*)(as + kk * 132 + (ty << 3) + 4);
            *(float4*)&w[0] = *(const float4*)(ws + kk * 132 + (tx << 3));
            *(float4*)&w[4] = *(const float4*)(ws + kk * 132 + (tx << 3) + 4);
            #pragma unroll
            for (int i = 0; i < 8; i++)
                #pragma unroll
                for (int j = 0; j < 8; j++)
                    acc[i][j] = fmaf(a[i], w[j], acc[i][j]);
        }

        if (t < 1) {
            float* asn = As[cur ^ 1]; float* wsn = Ws[cur ^ 1];
            asn[(ka+0)*132+lr]=a0.x; asn[(ka+1)*132+lr]=a0.y; asn[(ka+2)*132+lr]=a0.z; asn[(ka+3)*132+lr]=a0.w;
            asn[(ka+4)*132+lr]=a1.x; asn[(ka+5)*132+lr]=a1.y; asn[(ka+6)*132+lr]=a1.z; asn[(ka+7)*132+lr]=a1.w;
            wsn[(ka+0)*132+lr]=w0.x; wsn[(ka+1)*132+lr]=w0.y; wsn[(ka+2)*132+lr]=w0.z; wsn[(ka+3)*132+lr]=w0.w;
            wsn[(ka+4)*132+lr]=w1.x; wsn[(ka+5)*132+lr]=w1.y; wsn[(ka+6)*132+lr]=w1.z; wsn[(ka+7)*132+lr]=w1.w;
            __syncthreads();
        }
    }

    #pragma unroll
    for (int i = 0; i < 8; i++) {
        const int row = (ty << 3) + i;
        *(float4*)(outp + row * 1024 + n0 + (tx << 3)) =
            make_float4(acc[i][0], acc[i][1], acc[i][2], acc[i][3]);
        *(float4*)(outp + row * 1024 + n0 + (tx << 3) + 4) =
            make_float4(acc[i][4], acc[i][5], acc[i][6], acc[i][7]);
    }
}

// ---------------------------------------------------------------------------
// Fused-kernel branch: paired full-K GEMM for p & o. Recomputes its own
// 64x512 h tile from d_part into a private scratch slab first (hidden under
// the trace stream), then runs the GEMM with fused activation epilogue.
// ---------------------------------------------------------------------------
__device__ __forceinline__ void gemm2_body(
    const float* __restrict__ x,  const float* __restrict__ h_last,
    const float* __restrict__ w_px, const float* __restrict__ w_ph,
    const float* __restrict__ w_ox, const float* __restrict__ w_oh,
    const float* __restrict__ b_g,  const float* __restrict__ b_r,
    const float* __restrict__ b_p,  const float* __restrict__ b_o,
    float* __restrict__ out, int bx, int tid)
{
    __shared__ float As[16][68];
    __shared__ float Ps[16][68];
    __shared__ float Os[16][68];

    const int j0 = (bx & 7) * 64;
    const int m0 = (bx >> 3) * 64;
    float* hvt = d_hv2[bx];

    // build this CTA's h tile: rows [m0, m0+64) x cols [0,512)
    for (int e = tid; e < 64 * 512; e += 256) {
        const int row = m0 + (e >> 9);
        const int j   = e & 511;
        const int og  = (row << 10) + j;
        float gp = b_g[j], rp = b_r[j];
        sum_partials(og, gp, rp);
        const Gate gt = gate_math(gp, rp, h_last[row * 512 + j]);
        hvt[e] = gt.h;
    }
    __syncthreads();

    const int lm  = tid & 63;
    const int lk4 = (tid >> 6) << 2;
    const int tx  = tid & 15;
    const int ty  = tid >> 4;

    float accP[4][4], accO[4][4];
    #pragma unroll
    for (int i = 0; i < 4; i++)
        #pragma unroll
        for (int j = 0; j < 4; j++) { accP[i][j] = 0.f; accO[i][j] = 0.f; }

    float4 av = *(const float4*)(x    + (m0 + lm) * 512 + lk4);
    float4 pv = *(const float4*)(w_px + (j0 + lm) * 512 + lk4);
    float4 ov = *(const float4*)(w_ox + (j0 + lm) * 512 + lk4);

    for (int kt = 0; kt < 1024; kt += 16) {
        __syncthreads();
        As[lk4 + 0][lm] = av.x; As[lk4 + 1][lm] = av.y;
        As[lk4 + 2][lm] = av.z; As[lk4 + 3][lm] = av.w;
        Ps[lk4 + 0][lm] = pv.x; Ps[lk4 + 1][lm] = pv.y;
        Ps[lk4 + 2][lm] = pv.z; Ps[lk4 + 3][lm] = pv.w;
        Os[lk4 + 0][lm] = ov.x; Os[lk4 + 1][lm] = ov.y;
        Os[lk4 + 2][lm] = ov.z; Os[lk4 + 3][lm] = ov.w;
        __syncthreads();

        const int kn = kt + 16;
        if (kn < 1024) {
            if (kn < 512) {
                av = *(const float4*)(x + (m0 + lm) * 512 + kn + lk4);
                pv = *(const float4*)(w_px + (j0 + lm) * 512 + kn + lk4);
                ov = *(const float4*)(w_ox + (j0 + lm) * 512 + kn + lk4);
            } else {
                const int kk2 = kn - 512;
                av = *(const float4*)(hvt + lm * 512 + kk2 + lk4);      // local rows
                pv = *(const float4*)(w_ph + (j0 + lm) * 512 + kk2 + lk4);
                ov = *(const float4*)(w_oh + (j0 + lm) * 512 + kk2 + lk4);
            }
        }

        #pragma unroll
        for (int kk = 0; kk < 16; kk++) {
            const float4 a = *(const float4*)&As[kk][ty << 2];
            const float4 p = *(const float4*)&Ps[kk][tx << 2];
            const float4 o = *(const float4*)&Os[kk][tx << 2];
            accP[0][0]=fmaf(a.x,p.x,accP[0][0]); accP[0][1]=fmaf(a.x,p.y,accP[0][1]);
            accP[0][2]=fmaf(a.x,p.z,accP[0][2]); accP[0][3]=fmaf(a.x,p.w,accP[0][3]);
            accP[1][0]=fmaf(a.y,p.x,accP[1][0]); accP[1][1]=fmaf(a.y,p.y,accP[1][1]);
            accP[1][2]=fmaf(a.y,p.z,accP[1][2]); accP[1][3]=fmaf(a.y,p.w,accP[1][3]);
            accP[2][0]=fmaf(a.z,p.x,accP[2][0]); accP[2][1]=fmaf(a.z,p.y,accP[2][1]);
            accP[2][2]=fmaf(a.z,p.z,accP[2][2]); accP[2][3]=fmaf(a.z,p.w,accP[2][3]);
            accP[3][0]=fmaf(a.w,p.x,accP[3][0]); accP[3][1]=fmaf(a.w,p.y,accP[3][1]);
            accP[3][2]=fmaf(a.w,p.z,accP[3][2]); accP[3][3]=fmaf(a.w,p.w,accP[3][3]);
            accO[0][0]=fmaf(a.x,o.x,accO[0][0]); accO[0][1]=fmaf(a.x,o.y,accO[0][1]);
            accO[0][2]=fmaf(a.x,o.z,accO[0][2]); accO[0][3]=fmaf(a.x,o.w,accO[0][3]);
            accO[1][0]=fmaf(a.y,o.x,accO[1][0]); accO[1][1]=fmaf(a.y,o.y,accO[1][1]);
            accO[1][2]=fmaf(a.y,o.z,accO[1][2]); accO[1][3]=fmaf(a.y,o.w,accO[1][3]);
            accO[2][0]=fmaf(a.z,o.x,accO[2][0]); accO[2][1]=fmaf(a.z,o.y,accO[2][1]);
            accO[2][2]=fmaf(a.z,o.z,accO[2][2]); accO[2][3]=fmaf(a.z,o.w,accO[2][3]);
            accO[3][0]=fmaf(a.w,o.x,accO[3][0]); accO[3][1]=fmaf(a.w,o.y,accO[3][1]);
            accO[3][2]=fmaf(a.w,o.z,accO[3][2]); accO[3][3]=fmaf(a.w,o.w,accO[3][3]);
        }
    }

    #pragma unroll
    for (int i = 0; i < 4; i++) {
        float4 v;
        #pragma unroll
        for (int j = 0; j < 4; j++) {
            const int jj = j0 + (tx << 2) + j;
            const float pre_p = accP[i][j] + b_p[jj];
            const float pre_o = accO[i][j] + b_o[jj];
            const float pval  = tanhf(pre_p);
            const float oval  = 1.f / (1.f + expf(-pre_o));
            ((float*)&v)[j] = oval * pval;
        }
        *(float4*)(out + (m0 + (ty << 2) + i) * 512 + j0 + (tx << 2)) = v;
    }
}

// ---------------------------------------------------------------------------
// Fused-kernel branch: gate outputs (h, e_b_g, e_b_r) + openings counting.
// ---------------------------------------------------------------------------
__device__ __forceinline__ void gateout_body(
    int blk, int tid,
    const float* __restrict__ h_last,
    const float* __restrict__ b_g, const float* __restrict__ b_r,
    const float* __restrict__ e_b_g, const float* __restrict__ e_b_r,
    float* __restrict__ out_h, float* __restrict__ out_ebg,
    float* __restrict__ out_ebr, float* __restrict__ o_open)
{
    __shared__ int scnt[8];
    const int idx = blk * 256 + tid;     // b*512 + j
    const int b = idx >> 9;
    const int j = idx & 511;
    const int og = b * 1024 + j;

    float gp = b_g[j], rp = b_r[j];
    sum_partials(og, gp, rp);
    const Gate gt = gate_math(gp, rp, h_last[idx]);

    out_h[idx]   = gt.h;
    out_ebg[idx] = e_b_g[idx] * gt.a + gt.cg;
    out_ebr[idx] = e_b_r[idx] * gt.a + gt.cr;

    const int cnt = __popc(__ballot_sync(0xffffffffu, gt.g > 0.f));
    if ((tid & 31) == 0) scnt[tid >> 5] = cnt;
    __syncthreads();
    if (tid == 0) {
        int t = 0;
        #pragma unroll
        for (int w = 0; w < 8; w++) t += scnt[w];
        atomicAdd(&d_open, t);
        __threadfence();
        const int ticket = atomicAdd(&d_tick, 1);
        if (ticket == GATE_BLOCKS - 1) {
            const int total = atomicAdd(&d_open, 0);
            o_open[0] = (float)total * (1.f / (float)GATE_ELEMS);
        }
    }
}

// ---------------------------------------------------------------------------
// Fused-kernel branch: trace streamer. Block covers 2 (b,j) rows; warps 0-3
// recompute the gate coefficients for those rows from d_part, then all 256
// threads stream the 4 trace tensors.
// ---------------------------------------------------------------------------
__device__ __forceinline__ void trace_block(
    int tb, int tid,
    const float* __restrict__ x,  const float* __restrict__ hl,
    const float* __restrict__ b_g, const float* __restrict__ b_r,
    const float* __restrict__ egx, const float* __restrict__ egh,
    const float* __restrict__ erx, const float* __restrict__ erh,
    float* __restrict__ ogx, float* __restrict__ ogh,
    float* __restrict__ orx, float* __restrict__ orh)
{
    __shared__ float sh_pre[4];          // [row(2)][g/r]
    __shared__ float3 sh_c[2];           // (a, cg, cr) per row
    const int bj0 = tb * 2;

    const int w = tid >> 5;
    if (w < 4) {
        const int lrow = w >> 1;
        const int bj = bj0 + lrow;
        const int base = ((bj >> 9) << 10) + (bj & 511) + ((w & 1) ? 512 : 0);
        float v = d_part[tid & 31][base];
        #pragma unroll
        for (int o = 16; o; o >>= 1) v += __shfl_xor_sync(0xffffffffu, v, o);
        if ((tid & 31) == 0) sh_pre[w] = v;
    }
    __syncthreads();
    if (tid < 2) {
        const int bj = bj0 + tid;
        const int j = bj & 511;
        const Gate gt = gate_math(sh_pre[tid * 2] + b_g[j],
                                  sh_pre[tid * 2 + 1] + b_r[j],
                                  hl[bj]);
        sh_c[tid] = make_float3(gt.a, gt.cg, gt.cr);
    }
    __syncthreads();

    const int lrow = tid >> 7;           // 0/1
    const int bj = bj0 + lrow;
    const int b  = bj >> 9;
    const int i  = (tid & 127) << 2;     // column (float4 aligned)

    const float a  = sh_c[lrow].x;
    const float cg = sh_c[lrow].y;
    const float cr = sh_c[lrow].z;

    const float4 xv = *(const float4*)(x  + (b << 9) + i);
    const float4 hv = *(const float4*)(hl + (b << 9) + i);
    const int off = (bj << 9) + i;

    float4 e, t;

    e = *(const float4*)(egx + off);
    t.x = e.x * a + cg * xv.x; t.y = e.y * a + cg * xv.y;
    t.z = e.z * a + cg * xv.z; t.w = e.w * a + cg * xv.w;
    *(float4*)(ogx + off) = t;

    e = *(const float4*)(egh + off);
    t.x = e.x * a + cg * hv.x; t.y = e.y * a + cg * hv.y;
    t.z = e.z * a + cg * hv.z; t.w = e.w * a + cg * hv.w;
    *(float4*)(ogh + off) = t;

    e = *(const float4*)(erx + off);
    t.x = e.x * a + cr * xv.x; t.y = e.y * a + cr * xv.y;
    t.z = e.z * a + cr * xv.z; t.w = e.w * a + cr * xv.w;
    *(float4*)(orx + off) = t;

    e = *(const float4*)(erh + off);
    t.x = e.x * a + cr * hv.x; t.y = e.y * a + cr * hv.y;
    t.z = e.z * a + cr * hv.z; t.w = e.w * a + cr * hv.w;
    *(float4*)(orh + off) = t;
}

// ---------------------------------------------------------------------------
// Launch 2: everything after GEMM1, one kernel.
//   blocks [0,16)       : paired p/o GEMM (+ own h recompute) -> out
//   blocks [16,272)     : gate outputs h/e_b + openings
//   blocks [272,33040)  : HBM-bound trace stream (own coefficient recompute)
// ---------------------------------------------------------------------------
__global__ void __launch_bounds__(256) k_fused(
    const float* __restrict__ x,  const float* __restrict__ h_last,
    const float* __restrict__ w_px, const float* __restrict__ w_ph,
    const float* __restrict__ w_ox, const float* __restrict__ w_oh,
    const float* __restrict__ b_g,  const float* __restrict__ b_r,
    const float* __restrict__ b_p,  const float* __restrict__ b_o,
    const float* __restrict__ e_b_g, const float* __restrict__ e_b_r,
    const float* __restrict__ egx, const float* __restrict__ egh,
    const float* __restrict__ erx, const float* __restrict__ erh,
    float* __restrict__ ogx, float* __restrict__ ogh,
    float* __restrict__ orx, float* __restrict__ orh,
    float* __restrict__ o_out, float* __restrict__ o_h,
    float* __restrict__ o_ebg, float* __restrict__ o_ebr,
    float* __restrict__ o_open)
{
    const int bx = blockIdx.x;
    if (bx >= GEMM2_BLOCKS + GATE_BLOCKS) {
        trace_block(bx - GEMM2_BLOCKS - GATE_BLOCKS, threadIdx.x,
                    x, h_last, b_g, b_r,
                    egx, egh, erx, erh, ogx, ogh, orx, orh);
    } else if (bx >= GEMM2_BLOCKS) {
        gateout_body(bx - GEMM2_BLOCKS, threadIdx.x, h_last, b_g, b_r,
                     e_b_g, e_b_r, o_h, o_ebg, o_ebr, o_open);
    } else {
        gemm2_body(x, h_last, w_px, w_ph, w_ox, w_oh,
                   b_g, b_r, b_p, b_o, o_out, bx, threadIdx.x);
    }
}

// ---------------------------------------------------------------------------
extern "C" void kernel_launch(void* const* d_in, const int* in_sizes, int n_in,
                              void* d_out, int out_size)
{
    const float* x      = (const float*)d_in[0];
    const float* h_last = (const float*)d_in[1];
    const float* w_gx   = (const float*)d_in[2];
    const float* w_gh   = (const float*)d_in[3];
    const float* b_g    = (const float*)d_in[4];
    const float* w_rx   = (const float*)d_in[5];
    const float* w_rh   = (const float*)d_in[6];
    const float* b_r    = (const float*)d_in[7];
    const float* w_px   = (const float*)d_in[8];
    const float* w_ph   = (const float*)d_in[9];
    const float* b_p    = (const float*)d_in[10];
    const float* w_ox   = (const float*)d_in[11];
    const float* w_oh   = (const float*)d_in[12];
    const float* b_o    = (const float*)d_in[13];
    const float* e_w_gx = (const float*)d_in[14];
    const float* e_w_gh = (const float*)d_in[15];
    const float* e_b_g  = (const float*)d_in[16];
    const float* e_w_rx = (const float*)d_in[17];
    const float* e_w_rh = (const float*)d_in[18];
    const float* e_b_r  = (const float*)d_in[19];

    float* out    = (float*)d_out;
    float* o_out  = out;                  // (128,512)
    float* o_h    = out + 65536;          // (128,512)
    float* o_egx  = out + 131072;         // (128,512,512)
    float* o_egh  = out + 33685504;       // (128,512,512)
    float* o_ebg  = out + 67239936;       // (128,512)
    float* o_erx  = out + 67305472;       // (128,512,512)
    float* o_erh  = out + 100859904;      // (128,512,512)
    float* o_ebr  = out + 134414336;      // (128,512)
    float* o_open = out + 134479872;      // scalar

    // Launch 1: g/r pre-activations, split-K=32, 256 CTAs (2/SM resident)
    k_gemm1<<<dim3(8, NSPLIT), 256>>>(x, h_last, w_gx, w_gh, w_rx, w_rh);

    // Launch 2: everything else, dominated by the HBM trace stream
    k_fused<<<GEMM2_BLOCKS + GATE_BLOCKS + TRACE_BLOCKS, 256>>>(
        x, h_last, w_px, w_ph, w_ox, w_oh,
        b_g, b_r, b_p, b_o, e_b_g, e_b_r,
        e_w_gx, e_w_gh, e_w_rx, e_w_rh,
        o_egx, o_egh, o_erx, o_erh,
        o_out, o_h, o_ebg, o_ebr, o_open);
}

// round 8
// speedup vs baseline: 1.7599x; 1.7599x over previous
#include <cuda_runtime.h>
#include <math.h>

#define NB   128
#define NHID 512
#define GATE_ELEMS (NB * NHID)   // 65536
#define NSPLIT 32
#define GEMM1_BLOCKS (8 * NSPLIT)  // 256, all co-resident at 2 CTAs/SM
#define GEMM2_BLOCKS 16            // 8 j-tiles * 2 m-tiles (paired p/o, full-K)
#define TRACE_BLOCKS 32768

// ---------------- device scratch (no allocations allowed) ----------------
__device__ float d_part[NSPLIT][NB * 1024];  // split-K partials, 16 MB
__device__ float d_av  [GATE_ELEMS];         // 1 - g
__device__ float d_cgv [GATE_ELEMS];         // dg * delta_h
__device__ float d_crv [GATE_ELEMS];         // dr * g
__device__ float d_hv  [GATE_ELEMS];         // new h
__device__ int   d_cnt [GEMM1_BLOCKS];       // per-block open counts
__device__ int   d_done;                     // grid barrier counter (reset by k_fused)

// ---------------------------------------------------------------------------
// Launch 1: split-K dual GEMM for g/r pre-activations + in-kernel gate epilogue.
//   CTA tile 128m x 128n, BK=16, 8x8 register tile, double-buffered.
//   grid = (8 n-tiles, 32 splits) = 256 CTAs, 2 resident/SM (guaranteed).
//   After partials are stored, a device-wide ticket barrier releases all
//   blocks into the gate epilogue (each block: 256 elements).
// ---------------------------------------------------------------------------
__global__ void __launch_bounds__(256, 2) k_gemm1(
    const float* __restrict__ x, const float* __restrict__ h_last,
    const float* __restrict__ w_gx, const float* __restrict__ w_gh,
    const float* __restrict__ w_rx, const float* __restrict__ w_rh,
    const float* __restrict__ b_g,  const float* __restrict__ b_r,
    const float* __restrict__ e_b_g, const float* __restrict__ e_b_r,
    float* __restrict__ out_h, float* __restrict__ out_ebg,
    float* __restrict__ out_ebr)
{
    __shared__ float As[2][16 * 132];   // [stage][k][m(128)+pad]
    __shared__ float Ws[2][16 * 132];   // [stage][k][n(128)+pad]

    const int tid  = threadIdx.x;
    const int n0   = blockIdx.x * 128;   // n in [0,1024)
    const int s    = blockIdx.y;         // split 0..31
    const int half = s >> 4;             // 0: x-part, 1: h-part
    const int kb   = (s & 15) * 32;      // offset within the 512-wide half

    const bool g2 = (n0 >= 512);
    const int  j0 = g2 ? (n0 - 512) : n0;
    const float* A = half ? h_last : x;
    const float* W = g2 ? (half ? w_rh : w_rx) : (half ? w_gh : w_gx);
    float* outp    = d_part[s];

    const int lr = tid & 127;            // row (m for A, n for W)
    const int ka = (tid >> 7) << 3;      // k offset: 0 or 8 (two float4 each)

    const int tx = tid & 15;             // n-dir (8 cols)
    const int ty = tid >> 4;             // m-dir (8 rows)

    const float* Aload = A + lr * 512 + kb + ka;
    const float* Wload = W + (j0 + lr) * 512 + kb + ka;

    float acc[8][8];
    #pragma unroll
    for (int i = 0; i < 8; i++)
        #pragma unroll
        for (int j = 0; j < 8; j++) acc[i][j] = 0.f;

    float4 a0 = *(const float4*)(Aload);
    float4 a1 = *(const float4*)(Aload + 4);
    float4 w0 = *(const float4*)(Wload);
    float4 w1 = *(const float4*)(Wload + 4);

    {
        float* as = As[0]; float* ws = Ws[0];
        as[(ka+0)*132+lr]=a0.x; as[(ka+1)*132+lr]=a0.y; as[(ka+2)*132+lr]=a0.z; as[(ka+3)*132+lr]=a0.w;
        as[(ka+4)*132+lr]=a1.x; as[(ka+5)*132+lr]=a1.y; as[(ka+6)*132+lr]=a1.z; as[(ka+7)*132+lr]=a1.w;
        ws[(ka+0)*132+lr]=w0.x; ws[(ka+1)*132+lr]=w0.y; ws[(ka+2)*132+lr]=w0.z; ws[(ka+3)*132+lr]=w0.w;
        ws[(ka+4)*132+lr]=w1.x; ws[(ka+5)*132+lr]=w1.y; ws[(ka+6)*132+lr]=w1.z; ws[(ka+7)*132+lr]=w1.w;
    }
    __syncthreads();

    #pragma unroll 1
    for (int t = 0; t < 2; t++) {        // 2 k-tiles of 16 (k-chunk = 32)
        const int cur = t & 1;
        const float* as = As[cur];
        const float* ws = Ws[cur];

        if (t < 1) {                      // prefetch next k-tile
            a0 = *(const float4*)(Aload + 16);
            a1 = *(const float4*)(Aload + 20);
            w0 = *(const float4*)(Wload + 16);
            w1 = *(const float4*)(Wload + 20);
        }

        #pragma unroll
        for (int kk = 0; kk < 16; kk++) {
            float a[8], w[8];
            *(float4*)&a[0] = *(const float4*)(as + kk * 132 + (ty << 3));
            *(float4*)&a[4] = *(const float4*)(as + kk * 132 + (ty << 3) + 4);
            *(float4*)&w[0] = *(const float4*)(ws + kk * 132 + (tx << 3));
            *(float4*)&w[4] = *(const float4*)(ws + kk * 132 + (tx << 3) + 4);
            #pragma unroll
            for (int i = 0; i < 8; i++)
                #pragma unroll
                for (int j = 0; j < 8; j++)
                    acc[i][j] = fmaf(a[i], w[j], acc[i][j]);
        }

        if (t < 1) {
            float* asn = As[cur ^ 1]; float* wsn = Ws[cur ^ 1];
            asn[(ka+0)*132+lr]=a0.x; asn[(ka+1)*132+lr]=a0.y; asn[(ka+2)*132+lr]=a0.z; asn[(ka+3)*132+lr]=a0.w;
            asn[(ka+4)*132+lr]=a1.x; asn[(ka+5)*132+lr]=a1.y; asn[(ka+6)*132+lr]=a1.z; asn[(ka+7)*132+lr]=a1.w;
            wsn[(ka+0)*132+lr]=w0.x; wsn[(ka+1)*132+lr]=w0.y; wsn[(ka+2)*132+lr]=w0.z; wsn[(ka+3)*132+lr]=w0.w;
            wsn[(ka+4)*132+lr]=w1.x; wsn[(ka+5)*132+lr]=w1.y; wsn[(ka+6)*132+lr]=w1.z; wsn[(ka+7)*132+lr]=w1.w;
            __syncthreads();
        }
    }

    #pragma unroll
    for (int i = 0; i < 8; i++) {
        const int row = (ty << 3) + i;
        *(float4*)(outp + row * 1024 + n0 + (tx << 3)) =
            make_float4(acc[i][0], acc[i][1], acc[i][2], acc[i][3]);
        *(float4*)(outp + row * 1024 + n0 + (tx << 3) + 4) =
            make_float4(acc[i][4], acc[i][5], acc[i][6], acc[i][7]);
    }

    // ---- device-wide barrier: all 256 CTAs are co-resident (2/SM) ----
    __threadfence();
    __syncthreads();
    if (tid == 0) {
        atomicAdd(&d_done, 1);
        while (atomicAdd(&d_done, 0) < GEMM1_BLOCKS) { }
        __threadfence();
    }
    __syncthreads();

    // ---- gate epilogue: this block's 256 elements ----
    __shared__ int scnt[8];
    const int blk = blockIdx.y * 8 + blockIdx.x;   // 0..255
    const int idx = blk * 256 + tid;               // b*512 + j
    const int b = idx >> 9;
    const int j = idx & 511;
    const int og  = b * 1024 + j;
    const int orr = og + 512;

    float gpre = b_g[j], rpre = b_r[j];
    #pragma unroll
    for (int p = 0; p < NSPLIT; p++) {
        gpre += d_part[p][og];
        rpre += d_part[p][orr];
    }

    float g = tanhf(gpre);
    g = fmaxf(g, 0.f);                      // relu(tanh)
    const float r  = tanhf(rpre);
    const float hl = h_last[idx];
    const float h  = g * r + (1.f - g) * hl;
    const float Hg = (g > 0.f) ? 1.f : 0.f; // clip(ceil(g),0,1), g in [0,1]
    const float dg = (1.f - g * g) * Hg;
    const float dr = 1.f - r * r;
    const float a  = 1.f - g;
    const float cg = dg * (r - hl);
    const float cr = dr * g;

    d_av[idx]  = a;
    d_cgv[idx] = cg;
    d_crv[idx] = cr;
    d_hv[idx]  = h;

    out_h[idx]   = h;
    out_ebg[idx] = e_b_g[idx] * a + cg;
    out_ebr[idx] = e_b_r[idx] * a + cr;

    const int cnt = __popc(__ballot_sync(0xffffffffu, g > 0.f));
    if ((tid & 31) == 0) scnt[tid >> 5] = cnt;
    __syncthreads();
    if (tid == 0) {
        int t = 0;
        #pragma unroll
        for (int w = 0; w < 8; w++) t += scnt[w];
        d_cnt[blk] = t;
    }
}

// ---------------------------------------------------------------------------
// Paired full-K GEMM for p & o with fused activation epilogue (hidden under
// the trace stream inside k_fused).
// ---------------------------------------------------------------------------
__device__ __forceinline__ void gemm2_body(
    const float* __restrict__ x,
    const float* __restrict__ w_px, const float* __restrict__ w_ph,
    const float* __restrict__ w_ox, const float* __restrict__ w_oh,
    const float* __restrict__ b_p,  const float* __restrict__ b_o,
    float* __restrict__ out, int bx, int tid)
{
    __shared__ float As[16][68];
    __shared__ float Ps[16][68];
    __shared__ float Os[16][68];

    const int j0 = (bx & 7) * 64;
    const int m0 = (bx >> 3) * 64;

    const int lm  = tid & 63;
    const int lk4 = (tid >> 6) << 2;
    const int tx  = tid & 15;
    const int ty  = tid >> 4;

    float accP[4][4], accO[4][4];
    #pragma unroll
    for (int i = 0; i < 4; i++)
        #pragma unroll
        for (int j = 0; j < 4; j++) { accP[i][j] = 0.f; accO[i][j] = 0.f; }

    float4 av = *(const float4*)(x    + (m0 + lm) * 512 + lk4);
    float4 pv = *(const float4*)(w_px + (j0 + lm) * 512 + lk4);
    float4 ov = *(const float4*)(w_ox + (j0 + lm) * 512 + lk4);

    for (int kt = 0; kt < 1024; kt += 16) {
        __syncthreads();
        As[lk4 + 0][lm] = av.x; As[lk4 + 1][lm] = av.y;
        As[lk4 + 2][lm] = av.z; As[lk4 + 3][lm] = av.w;
        Ps[lk4 + 0][lm] = pv.x; Ps[lk4 + 1][lm] = pv.y;
        Ps[lk4 + 2][lm] = pv.z; Ps[lk4 + 3][lm] = pv.w;
        Os[lk4 + 0][lm] = ov.x; Os[lk4 + 1][lm] = ov.y;
        Os[lk4 + 2][lm] = ov.z; Os[lk4 + 3][lm] = ov.w;
        __syncthreads();

        const int kn = kt + 16;
        if (kn < 1024) {
            const int kk2 = (kn < 512) ? kn : (kn - 512);
            const float* An = (kn < 512) ? x    : d_hv;
            const float* Pn = (kn < 512) ? w_px : w_ph;
            const float* On = (kn < 512) ? w_ox : w_oh;
            av = *(const float4*)(An + (m0 + lm) * 512 + kk2 + lk4);
            pv = *(const float4*)(Pn + (j0 + lm) * 512 + kk2 + lk4);
            ov = *(const float4*)(On + (j0 + lm) * 512 + kk2 + lk4);
        }

        #pragma unroll
        for (int kk = 0; kk < 16; kk++) {
            const float4 a = *(const float4*)&As[kk][ty << 2];
            const float4 p = *(const float4*)&Ps[kk][tx << 2];
            const float4 o = *(const float4*)&Os[kk][tx << 2];
            accP[0][0]=fmaf(a.x,p.x,accP[0][0]); accP[0][1]=fmaf(a.x,p.y,accP[0][1]);
            accP[0][2]=fmaf(a.x,p.z,accP[0][2]); accP[0][3]=fmaf(a.x,p.w,accP[0][3]);
            accP[1][0]=fmaf(a.y,p.x,accP[1][0]); accP[1][1]=fmaf(a.y,p.y,accP[1][1]);
            accP[1][2]=fmaf(a.y,p.z,accP[1][2]); accP[1][3]=fmaf(a.y,p.w,accP[1][3]);
            accP[2][0]=fmaf(a.z,p.x,accP[2][0]); accP[2][1]=fmaf(a.z,p.y,accP[2][1]);
            accP[2][2]=fmaf(a.z,p.z,accP[2][2]); accP[2][3]=fmaf(a.z,p.w,accP[2][3]);
            accP[3][0]=fmaf(a.w,p.x,accP[3][0]); accP[3][1]=fmaf(a.w,p.y,accP[3][1]);
            accP[3][2]=fmaf(a.w,p.z,accP[3][2]); accP[3][3]=fmaf(a.w,p.w,accP[3][3]);
            accO[0][0]=fmaf(a.x,o.x,accO[0][0]); accO[0][1]=fmaf(a.x,o.y,accO[0][1]);
            accO[0][2]=fmaf(a.x,o.z,accO[0][2]); accO[0][3]=fmaf(a.x,o.w,accO[0][3]);
            accO[1][0]=fmaf(a.y,o.x,accO[1][0]); accO[1][1]=fmaf(a.y,o.y,accO[1][1]);
            accO[1][2]=fmaf(a.y,o.z,accO[1][2]); accO[1][3]=fmaf(a.y,o.w,accO[1][3]);
            accO[2][0]=fmaf(a.z,o.x,accO[2][0]); accO[2][1]=fmaf(a.z,o.y,accO[2][1]);
            accO[2][2]=fmaf(a.z,o.z,accO[2][2]); accO[2][3]=fmaf(a.z,o.w,accO[2][3]);
            accO[3][0]=fmaf(a.w,o.x,accO[3][0]); accO[3][1]=fmaf(a.w,o.y,accO[3][1]);
            accO[3][2]=fmaf(a.w,o.z,accO[3][2]); accO[3][3]=fmaf(a.w,o.w,accO[3][3]);
        }
    }

    #pragma unroll
    for (int i = 0; i < 4; i++) {
        float4 v;
        #pragma unroll
        for (int j = 0; j < 4; j++) {
            const int jj = j0 + (tx << 2) + j;
            const float pre_p = accP[i][j] + b_p[jj];
            const float pre_o = accO[i][j] + b_o[jj];
            const float pval  = tanhf(pre_p);
            const float oval  = 1.f / (1.f + expf(-pre_o));
            ((float*)&v)[j] = oval * pval;
        }
        *(float4*)(out + (m0 + (ty << 2) + i) * 512 + j0 + (tx << 2)) = v;
    }
}

// Trace row update body: LDGs issue at block start (no head work).
__device__ __forceinline__ void trace_body(
    int idx,
    const float* __restrict__ x,  const float* __restrict__ hl,
    const float* __restrict__ egx, const float* __restrict__ egh,
    const float* __restrict__ erx, const float* __restrict__ erh,
    float* __restrict__ ogx, float* __restrict__ ogh,
    float* __restrict__ orx, float* __restrict__ orh)
{
    const int i   = (idx & 127) << 2;
    const int bj  = idx >> 7;
    const int b   = bj >> 9;

    const float a  = __ldg(&d_av[bj]);
    const float cg = __ldg(&d_cgv[bj]);
    const float cr = __ldg(&d_crv[bj]);

    const float4 xv = *(const float4*)(x  + (b << 9) + i);
    const float4 hv = *(const float4*)(hl + (b << 9) + i);
    const int off = (bj << 9) + i;

    float4 e, t;

    e = *(const float4*)(egx + off);
    t.x = e.x * a + cg * xv.x; t.y = e.y * a + cg * xv.y;
    t.z = e.z * a + cg * xv.z; t.w = e.w * a + cg * xv.w;
    *(float4*)(ogx + off) = t;

    e = *(const float4*)(egh + off);
    t.x = e.x * a + cg * hv.x; t.y = e.y * a + cg * hv.y;
    t.z = e.z * a + cg * hv.z; t.w = e.w * a + cg * hv.w;
    *(float4*)(ogh + off) = t;

    e = *(const float4*)(erx + off);
    t.x = e.x * a + cr * xv.x; t.y = e.y * a + cr * xv.y;
    t.z = e.z * a + cr * xv.z; t.w = e.w * a + cr * xv.w;
    *(float4*)(orx + off) = t;

    e = *(const float4*)(erh + off);
    t.x = e.x * a + cr * hv.x; t.y = e.y * a + cr * hv.y;
    t.z = e.z * a + cr * hv.z; t.w = e.w * a + cr * hv.w;
    *(float4*)(orh + off) = t;
}

// ---------------------------------------------------------------------------
// Launch 2: FUSED kernel.
//   blocks [0, 16)        : paired p/o GEMM, fused activation -> out
//   blocks [16, 16+32768) : HBM-bound trace update
//   block  16+32768       : openings scalar from d_cnt + reset d_done
// ---------------------------------------------------------------------------
__global__ void __launch_bounds__(256) k_fused(
    const float* __restrict__ x,  const float* __restrict__ h_last,
    const float* __restrict__ w_px, const float* __restrict__ w_ph,
    const float* __restrict__ w_ox, const float* __restrict__ w_oh,
    const float* __restrict__ b_p,  const float* __restrict__ b_o,
    const float* __restrict__ egx, const float* __restrict__ egh,
    const float* __restrict__ erx, const float* __restrict__ erh,
    float* __restrict__ ogx, float* __restrict__ ogh,
    float* __restrict__ orx, float* __restrict__ orh,
    float* __restrict__ o_out, float* __restrict__ o_open)
{
    const int bx = blockIdx.x;
    if (bx < GEMM2_BLOCKS) {
        gemm2_body(x, w_px, w_ph, w_ox, w_oh, b_p, b_o, o_out, bx, threadIdx.x);
    } else if (bx < GEMM2_BLOCKS + TRACE_BLOCKS) {
        const int idx = (bx - GEMM2_BLOCKS) * 256 + threadIdx.x;
        trace_body(idx, x, h_last, egx, egh, erx, erh, ogx, ogh, orx, orh);
    } else {
        __shared__ int scnt[256];
        scnt[threadIdx.x] = d_cnt[threadIdx.x];
        __syncthreads();
        for (int st = 128; st > 0; st >>= 1) {
            if (threadIdx.x < st) scnt[threadIdx.x] += scnt[threadIdx.x + st];
            __syncthreads();
        }
        if (threadIdx.x == 0) {
            o_open[0] = (float)scnt[0] * (1.f / (float)GATE_ELEMS);
            d_done = 0;                  // reset grid barrier for next replay
        }
    }
}

// ---------------------------------------------------------------------------
extern "C" void kernel_launch(void* const* d_in, const int* in_sizes, int n_in,
                              void* d_out, int out_size)
{
    const float* x      = (const float*)d_in[0];
    const float* h_last = (const float*)d_in[1];
    const float* w_gx   = (const float*)d_in[2];
    const float* w_gh   = (const float*)d_in[3];
    const float* b_g    = (const float*)d_in[4];
    const float* w_rx   = (const float*)d_in[5];
    const float* w_rh   = (const float*)d_in[6];
    const float* b_r    = (const float*)d_in[7];
    const float* w_px   = (const float*)d_in[8];
    const float* w_ph   = (const float*)d_in[9];
    const float* b_p    = (const float*)d_in[10];
    const float* w_ox   = (const float*)d_in[11];
    const float* w_oh   = (const float*)d_in[12];
    const float* b_o    = (const float*)d_in[13];
    const float* e_w_gx = (const float*)d_in[14];
    const float* e_w_gh = (const float*)d_in[15];
    const float* e_b_g  = (const float*)d_in[16];
    const float* e_w_rx = (const float*)d_in[17];
    const float* e_w_rh = (const float*)d_in[18];
    const float* e_b_r  = (const float*)d_in[19];

    float* out    = (float*)d_out;
    float* o_out  = out;                  // (128,512)
    float* o_h    = out + 65536;          // (128,512)
    float* o_egx  = out + 131072;         // (128,512,512)
    float* o_egh  = out + 33685504;       // (128,512,512)
    float* o_ebg  = out + 67239936;       // (128,512)
    float* o_erx  = out + 67305472;       // (128,512,512)
    float* o_erh  = out + 100859904;      // (128,512,512)
    float* o_ebr  = out + 134414336;      // (128,512)
    float* o_open = out + 134479872;      // scalar

    // Launch 1: g/r GEMM (split-K=32, 256 CTAs, 2/SM) + in-kernel gate epilogue
    k_gemm1<<<dim3(8, NSPLIT), 256>>>(x, h_last, w_gx, w_gh, w_rx, w_rh,
                                      b_g, b_r, e_b_g, e_b_r,
                                      o_h, o_ebg, o_ebr);

    // Launch 2: paired p/o GEMM (+activations) + trace streamer + openings
    k_fused<<<GEMM2_BLOCKS + TRACE_BLOCKS + 1, 256>>>(
        x, h_last, w_px, w_ph, w_ox, w_oh, b_p, b_o,
        e_w_gx, e_w_gh, e_w_rx, e_w_rh,
        o_egx, o_egh, o_erx, o_erh,
        o_out, o_open);
}